// round 5
// baseline (speedup 1.0000x reference)
#include <cuda_runtime.h>

#define K_CTX 64
#define D     128
#define DS    200
#define STRIDE 132    // padded smem row stride (words); 16B-aligned rows, conflict-free f4 loads

__device__ float g_AM[K_CTX * D];

__device__ __forceinline__ unsigned long long fma2(unsigned long long a,
                                                   unsigned long long b,
                                                   unsigned long long c) {
    unsigned long long d;
    asm("fma.rn.f32x2 %0, %1, %2, %3;" : "=l"(d) : "l"(a), "l"(b), "l"(c));
    return d;
}
__device__ __forceinline__ float unpack_add(unsigned long long v) {
    unsigned lo, hi;
    asm("mov.b64 {%0,%1}, %2;" : "=r"(lo), "=r"(hi) : "l"(v));
    return __uint_as_float(lo) + __uint_as_float(hi);
}
__device__ __forceinline__ float tanh_fast(float x) {
    x = fminf(fmaxf(x, -15.f), 15.f);
    float e = __expf(2.f * x);
    return __fdividef(e - 1.f, e + 1.f);
}

__global__ void prep_kernel(const float* __restrict__ table,
                            const float* __restrict__ att,
                            const int* __restrict__ t1_ctx) {
    __shared__ float sA[D];
    const int k = blockIdx.x;
    const int j = threadIdx.x;
    sA[j] = table[(size_t)t1_ctx[k] * D + j];
    __syncthreads();
    float acc = 0.f;
#pragma unroll 8
    for (int d = 0; d < D; ++d)
        acc = fmaf(sA[d], att[d * D + j], acc);
    g_AM[k * D + j] = acc;
}

__global__ __launch_bounds__(256, 2)
void main_kernel(const float* __restrict__ table,
                 const float* __restrict__ str_t1,
                 const float* __restrict__ str_t2s,
                 const float* __restrict__ W,
                 const float* __restrict__ b_bi,
                 const int* __restrict__ t1_ctx,
                 const int* __restrict__ t2_ctx,
                 float* __restrict__ out) {
    extern __shared__ float sm[];
    float* sAM     = sm;                        // 64*132
    float* sB      = sAM + K_CTX * STRIDE;      // 64*132
    float* rw      = sB  + K_CTX * STRIDE;      // 64
    float* cw      = rw  + 64;                  // 64
    float* colpart = cw  + 64;                  // 8*64
    float* nA      = colpart + 512;             // 128
    float* nB      = nA  + 128;                 // 128
    float* red     = nB  + 128;                 // 256
    float* part    = red + 256;                 // 32 (4 bilinear + 3*8 string)

    __shared__ int sIdx[K_CTX];

    const int t = threadIdx.x;
    const int c = blockIdx.x;
    const int lane = t & 31;

    // ---- string-branch inputs: issue loads early, consume at the end ----
    float x1 = 0.f, x2 = 0.f;
    if (t < DS) { x1 = str_t1[t]; x2 = str_t2s[c * DS + t]; }

    if (t < K_CTX) sIdx[t] = t1_ctx[t];

    for (int i = t; i < K_CTX * D; i += 256)
        sAM[(i >> 7) * STRIDE + (i & 127)] = g_AM[i];

    // ---- gather B rows: 4 threads/row, each copies contiguous 128B via float4 ----
    {
        const int r = t >> 2, l = t & 3;
        size_t idx = (size_t)t2_ctx[c * K_CTX + r];
        const float4* src = (const float4*)(table + idx * D);
        float4* dst = (float4*)(sB + r * STRIDE);
#pragma unroll
        for (int q = 0; q < 8; ++q)
            dst[l * 8 + q] = src[l * 8 + q];
    }
    __syncthreads();

    // ---- S = tanh(AM @ B^T): 64x64x128, 4x4 tiles, f32x2 packed FMA ----
    const int tx = t & 15, ty = t >> 4;
    float sv[4][4];
    {
        const float* pa = sAM + ty * STRIDE;
        const float* pb = sB  + tx * STRIDE;
        unsigned long long acc[4][4];
#pragma unroll
        for (int p = 0; p < 4; ++p)
#pragma unroll
            for (int q = 0; q < 4; ++q) acc[p][q] = 0ull;

#pragma unroll 2
        for (int dd = 0; dd < D; dd += 4) {
            ulonglong2 A[4], B[4];
#pragma unroll
            for (int p = 0; p < 4; ++p)
                A[p] = *(const ulonglong2*)(pa + p * 16 * STRIDE + dd);
#pragma unroll
            for (int q = 0; q < 4; ++q)
                B[q] = *(const ulonglong2*)(pb + q * 16 * STRIDE + dd);
#pragma unroll
            for (int p = 0; p < 4; ++p)
#pragma unroll
                for (int q = 0; q < 4; ++q) {
                    acc[p][q] = fma2(A[p].x, B[q].x, acc[p][q]);
                    acc[p][q] = fma2(A[p].y, B[q].y, acc[p][q]);
                }
        }
#pragma unroll
        for (int p = 0; p < 4; ++p)
#pragma unroll
            for (int q = 0; q < 4; ++q)
                sv[p][q] = tanh_fast(unpack_add(acc[p][q]));
    }

    // ---- row sums (over m): in-register + shuffle over tx bits ----
    {
#pragma unroll
        for (int p = 0; p < 4; ++p) {
            float rs = sv[p][0] + sv[p][1] + sv[p][2] + sv[p][3];
            rs += __shfl_xor_sync(0xffffffffu, rs, 1);
            rs += __shfl_xor_sync(0xffffffffu, rs, 2);
            rs += __shfl_xor_sync(0xffffffffu, rs, 4);
            rs += __shfl_xor_sync(0xffffffffu, rs, 8);
            if (tx == 0) rw[ty + 16 * p] = rs * (1.f / 64.f);
        }
        // col partials (over k): sum p in-reg, pair ty via xor16, 8 warp partials
        const int w = t >> 5;
#pragma unroll
        for (int q = 0; q < 4; ++q) {
            float cs = sv[0][q] + sv[1][q] + sv[2][q] + sv[3][q];
            cs += __shfl_xor_sync(0xffffffffu, cs, 16);
            if (lane < 16) colpart[w * 64 + tx + 16 * q] = cs;
        }
    }
    __syncthreads();

    if (t >= 64 && t < 128) {
        const int m = t - 64;
        float s = 0.f;
#pragma unroll
        for (int w = 0; w < 8; ++w) s += colpart[w * 64 + m];
        cw[m] = s * (1.f / 64.f);
    }
    __syncthreads();

    // ---- dual softmax: warp0 -> rows, warp1 -> cols ----
    if (t < 64) {
        float* vec = (t < 32) ? rw : cw;
        float v0 = vec[lane], v1 = vec[lane + 32];
        float mx = fmaxf(v0, v1);
#pragma unroll
        for (int o = 16; o >= 1; o >>= 1)
            mx = fmaxf(mx, __shfl_xor_sync(0xffffffffu, mx, o));
        float e0 = __expf(v0 - mx), e1 = __expf(v1 - mx);
        float s = e0 + e1;
#pragma unroll
        for (int o = 16; o >= 1; o >>= 1)
            s += __shfl_xor_sync(0xffffffffu, s, o);
        float inv = __fdividef(1.f, s);
        vec[lane] = e0 * inv;
        vec[lane + 32] = e1 * inv;
    }
    __syncthreads();

    // ---- new_A (from L2-hot table rows), new_B (from smem) ----
    if (t < 128) {
        float s = 0.f;
#pragma unroll 4
        for (int k = 0; k < K_CTX; ++k)
            s = fmaf(rw[k], table[(size_t)sIdx[k] * D + t], s);
        nA[t] = s;
    } else {
        const int dd = t - 128;
        float s = 0.f;
#pragma unroll 4
        for (int k = 0; k < K_CTX; ++k)
            s = fmaf(cw[k], sB[k * STRIDE + dd], s);
        nB[dd] = s;
    }
    __syncthreads();

    // ---- bilinear: split d-range across the two thread halves ----
    {
        const int col = t & 127, half = t >> 7;
        float s = 0.f;
        const int d0 = half * 64;
#pragma unroll 4
        for (int d = d0; d < d0 + 64; ++d)
            s = fmaf(nA[d], W[d * D + col], s);
        red[t] = s;
    }
    __syncthreads();
    if (t < 128) {
        float v = (red[t] + red[t + 128]) * nB[t];
#pragma unroll
        for (int o = 16; o >= 1; o >>= 1)
            v += __shfl_xor_sync(0xffffffffu, v, o);
        if (lane == 0) part[t >> 5] = v;
    }
    __syncthreads();

    // ---- string cosine branch: shuffle-reduce 3 dot products ----
    {
        float p11 = x1 * x1, p22 = x2 * x2, p12 = x1 * x2;
#pragma unroll
        for (int o = 16; o >= 1; o >>= 1) {
            p11 += __shfl_xor_sync(0xffffffffu, p11, o);
            p22 += __shfl_xor_sync(0xffffffffu, p22, o);
            p12 += __shfl_xor_sync(0xffffffffu, p12, o);
        }
        const int w = t >> 5;
        if (lane == 0) { part[8 + w] = p11; part[16 + w] = p22; part[24 + w] = p12; }
    }
    __syncthreads();

    if (t == 0) {
        float con = part[0] + part[1] + part[2] + part[3] + b_bi[0];
        float s11 = 0.f, s22 = 0.f, s12 = 0.f;
#pragma unroll
        for (int w = 0; w < 8; ++w) {
            s11 += part[8 + w]; s22 += part[16 + w]; s12 += part[24 + w];
        }
        float n1 = fmaxf(sqrtf(s11), 1e-8f);
        float n2 = fmaxf(sqrtf(s22), 1e-8f);
        float str_score = s12 / (n1 * n2);
        out[c] = 0.5f * str_score + 0.5f * con;
    }
}

static const int SMEM_BYTES =
    (K_CTX * STRIDE * 2 + 64 + 64 + 512 + 128 + 128 + 256 + 32) * 4;

extern "C" void kernel_launch(void* const* d_in, const int* in_sizes, int n_in,
                              void* d_out, int out_size) {
    const float* table   = (const float*)d_in[0];
    const float* str_t1  = (const float*)d_in[1];
    const float* str_t2s = (const float*)d_in[2];
    const float* att_mat = (const float*)d_in[3];
    const float* W_bi    = (const float*)d_in[4];
    const float* b_bi    = (const float*)d_in[5];
    const int*   t1_ctx  = (const int*)d_in[6];
    const int*   t2_ctx  = (const int*)d_in[7];
    float* out = (float*)d_out;

    cudaFuncSetAttribute(main_kernel,
                         cudaFuncAttributeMaxDynamicSharedMemorySize, SMEM_BYTES);

    prep_kernel<<<K_CTX, D>>>(table, att_mat, t1_ctx);
    main_kernel<<<256, 256, SMEM_BYTES>>>(table, str_t1, str_t2s, W_bi, b_bi,
                                          t1_ctx, t2_ctx, out);
}

// round 6
// speedup vs baseline: 1.1104x; 1.1104x over previous
#include <cuda_runtime.h>

#define K_CTX 64
#define D     128
#define DS    200
#define STRIDE 132   // words; 16B-aligned rows; 8-lane LDS.128 phases conflict-free

__device__ float g_AM[K_CTX * D];        // AM = table[t1_ctx] @ att_mat
__device__ float g_rowm[256 * K_CTX];    // raw row sums per candidate
__device__ float g_colp[512 * K_CTX];    // col partial sums per half-CTA

__device__ __forceinline__ float tanh_fast(float x) {
    x = fminf(fmaxf(x, -15.f), 15.f);
    float e = __expf(2.f * x);
    return __fdividef(e - 1.f, e + 1.f);
}

__global__ void prep_kernel(const float* __restrict__ table,
                            const float* __restrict__ att,
                            const int* __restrict__ t1_ctx) {
    __shared__ float sA[D];
    const int k = blockIdx.x;
    const int j = threadIdx.x;
    sA[j] = table[(size_t)t1_ctx[k] * D + j];
    __syncthreads();
    float acc = 0.f;
#pragma unroll 8
    for (int d = 0; d < D; ++d)
        acc = fmaf(sA[d], att[d * D + j], acc);
    g_AM[k * D + j] = acc;
}

// ---- Kernel A: half-candidate GEMM + tanh + row/col reductions ----
__global__ __launch_bounds__(256, 4)
void gemm_kernel(const float* __restrict__ table,
                 const int* __restrict__ t2_ctx) {
    extern __shared__ float sm[];
    float* sA      = sm;                    // 32*132
    float* sB      = sA + 32 * STRIDE;      // 64*132
    float* colpart = sB + K_CTX * STRIDE;   // 8*64

    const int t    = threadIdx.x;
    const int bid  = blockIdx.x;
    const int c    = bid >> 1;
    const int k0   = (bid & 1) << 5;        // 0 or 32
    const int lane = t & 31;

    // stage 32 AM rows for this half
    for (int i = t; i < 32 * D; i += 256)
        sA[(i >> 7) * STRIDE + (i & 127)] = g_AM[((k0 + (i >> 7)) << 7) + (i & 127)];

    // gather all 64 B rows: 4 threads/row, float4
    {
        const int r = t >> 2, l = t & 3;
        size_t idx = (size_t)t2_ctx[c * K_CTX + r];
        const float4* src = (const float4*)(table + idx * D);
        float4* dst = (float4*)(sB + r * STRIDE);
#pragma unroll
        for (int q = 0; q < 8; ++q)
            dst[l * 8 + q] = src[l * 8 + q];
    }
    __syncthreads();

    // 32x64x128 GEMM, 2x4 tiles: rows ty+16p, cols tx+16q
    const int tx = t & 15, ty = t >> 4;
    float acc[2][4];
#pragma unroll
    for (int p = 0; p < 2; ++p)
#pragma unroll
        for (int q = 0; q < 4; ++q) acc[p][q] = 0.f;

    {
        const float* pa = sA + ty * STRIDE;
        const float* pb = sB + tx * STRIDE;
#pragma unroll 2
        for (int dd = 0; dd < D; dd += 4) {
            float4 a0 = *(const float4*)(pa + dd);
            float4 a1 = *(const float4*)(pa + 16 * STRIDE + dd);
            float4 b0 = *(const float4*)(pb + dd);
            float4 b1 = *(const float4*)(pb + 16 * STRIDE + dd);
            float4 b2 = *(const float4*)(pb + 32 * STRIDE + dd);
            float4 b3 = *(const float4*)(pb + 48 * STRIDE + dd);
#define STEP(ax, bx) \
            acc[0][0] = fmaf(a0.ax, b0.ax, acc[0][0]); \
            acc[0][1] = fmaf(a0.ax, b1.ax, acc[0][1]); \
            acc[0][2] = fmaf(a0.ax, b2.ax, acc[0][2]); \
            acc[0][3] = fmaf(a0.ax, b3.ax, acc[0][3]); \
            acc[1][0] = fmaf(a1.ax, b0.ax, acc[1][0]); \
            acc[1][1] = fmaf(a1.ax, b1.ax, acc[1][1]); \
            acc[1][2] = fmaf(a1.ax, b2.ax, acc[1][2]); \
            acc[1][3] = fmaf(a1.ax, b3.ax, acc[1][3]);
            STEP(x, x) STEP(y, y) STEP(z, z) STEP(w, w)
#undef STEP
        }
    }

    float sv[2][4];
#pragma unroll
    for (int p = 0; p < 2; ++p)
#pragma unroll
        for (int q = 0; q < 4; ++q) sv[p][q] = tanh_fast(acc[p][q]);

    // row sums (over m): shuffle across tx bits
#pragma unroll
    for (int p = 0; p < 2; ++p) {
        float rs = sv[p][0] + sv[p][1] + sv[p][2] + sv[p][3];
        rs += __shfl_xor_sync(0xffffffffu, rs, 1);
        rs += __shfl_xor_sync(0xffffffffu, rs, 2);
        rs += __shfl_xor_sync(0xffffffffu, rs, 4);
        rs += __shfl_xor_sync(0xffffffffu, rs, 8);
        if (tx == 0) g_rowm[c * K_CTX + k0 + ty + 16 * p] = rs;
    }

    // col partials (over this half's 32 k): pair ty via xor16, 8 warp pieces
    {
        const int w = t >> 5;
#pragma unroll
        for (int q = 0; q < 4; ++q) {
            float cs = sv[0][q] + sv[1][q];
            cs += __shfl_xor_sync(0xffffffffu, cs, 16);
            if (lane < 16) colpart[w * 64 + tx + 16 * q] = cs;
        }
    }
    __syncthreads();
    if (t < 64) {
        float s = 0.f;
#pragma unroll
        for (int w = 0; w < 8; ++w) s += colpart[w * 64 + t];
        g_colp[bid * K_CTX + t] = s;
    }
}

// ---- Kernel B: softmax + attention sums + bilinear + string branch ----
__global__ __launch_bounds__(256)
void score_kernel(const float* __restrict__ table,
                  const float* __restrict__ str_t1,
                  const float* __restrict__ str_t2s,
                  const float* __restrict__ W,
                  const float* __restrict__ b_bi,
                  const int* __restrict__ t1_ctx,
                  const int* __restrict__ t2_ctx,
                  float* __restrict__ out) {
    __shared__ float rw[64], cw[64], nA[128], nB[128], red[256], part[32];
    __shared__ int sIdxA[64], sIdxB[64];

    const int t = threadIdx.x;
    const int c = blockIdx.x;
    const int lane = t & 31;

    float x1 = 0.f, x2 = 0.f;
    if (t < DS) { x1 = str_t1[t]; x2 = str_t2s[c * DS + t]; }

    if (t < 64) {
        sIdxA[t] = t1_ctx[t];
        rw[t] = g_rowm[c * K_CTX + t] * (1.f / 64.f);
    } else if (t < 128) {
        const int m = t - 64;
        sIdxB[m] = t2_ctx[c * K_CTX + m];
        cw[m] = (g_colp[(2 * c) * K_CTX + m] + g_colp[(2 * c + 1) * K_CTX + m])
                * (1.f / 64.f);
    }
    __syncthreads();

    // dual softmax: warp0 -> rows, warp1 -> cols
    if (t < 64) {
        float* vec = (t < 32) ? rw : cw;
        float v0 = vec[lane], v1 = vec[lane + 32];
        float mx = fmaxf(v0, v1);
#pragma unroll
        for (int o = 16; o >= 1; o >>= 1)
            mx = fmaxf(mx, __shfl_xor_sync(0xffffffffu, mx, o));
        float e0 = __expf(v0 - mx), e1 = __expf(v1 - mx);
        float s = e0 + e1;
#pragma unroll
        for (int o = 16; o >= 1; o >>= 1)
            s += __shfl_xor_sync(0xffffffffu, s, o);
        float inv = __fdividef(1.f, s);
        vec[lane] = e0 * inv;
        vec[lane + 32] = e1 * inv;
    }
    __syncthreads();

    // nA / nB from L2-hot table rows
    if (t < 128) {
        float s = 0.f;
#pragma unroll 4
        for (int k = 0; k < K_CTX; ++k)
            s = fmaf(rw[k], table[(size_t)sIdxA[k] * D + t], s);
        nA[t] = s;
    } else {
        const int dd = t - 128;
        float s = 0.f;
#pragma unroll 4
        for (int k = 0; k < K_CTX; ++k)
            s = fmaf(cw[k], table[(size_t)sIdxB[k] * D + dd], s);
        nB[dd] = s;
    }
    __syncthreads();

    // bilinear: split d across thread halves
    {
        const int col = t & 127, half = t >> 7;
        float s = 0.f;
        const int d0 = half * 64;
#pragma unroll 4
        for (int d = d0; d < d0 + 64; ++d)
            s = fmaf(nA[d], W[d * D + col], s);
        red[t] = s;
    }
    __syncthreads();
    if (t < 128) {
        float v = (red[t] + red[t + 128]) * nB[t];
#pragma unroll
        for (int o = 16; o >= 1; o >>= 1)
            v += __shfl_xor_sync(0xffffffffu, v, o);
        if (lane == 0) part[t >> 5] = v;
    }
    __syncthreads();

    // string cosine branch
    {
        float p11 = x1 * x1, p22 = x2 * x2, p12 = x1 * x2;
#pragma unroll
        for (int o = 16; o >= 1; o >>= 1) {
            p11 += __shfl_xor_sync(0xffffffffu, p11, o);
            p22 += __shfl_xor_sync(0xffffffffu, p22, o);
            p12 += __shfl_xor_sync(0xffffffffu, p12, o);
        }
        const int w = t >> 5;
        if (lane == 0) { part[8 + w] = p11; part[16 + w] = p22; part[24 + w] = p12; }
    }
    __syncthreads();

    if (t == 0) {
        float con = part[0] + part[1] + part[2] + part[3] + b_bi[0];
        float s11 = 0.f, s22 = 0.f, s12 = 0.f;
#pragma unroll
        for (int w = 0; w < 8; ++w) {
            s11 += part[8 + w]; s22 += part[16 + w]; s12 += part[24 + w];
        }
        float n1 = fmaxf(sqrtf(s11), 1e-8f);
        float n2 = fmaxf(sqrtf(s22), 1e-8f);
        out[c] = 0.5f * (s12 / (n1 * n2)) + 0.5f * con;
    }
}

static const int GEMM_SMEM = (32 * STRIDE + K_CTX * STRIDE + 8 * 64) * 4;

extern "C" void kernel_launch(void* const* d_in, const int* in_sizes, int n_in,
                              void* d_out, int out_size) {
    const float* table   = (const float*)d_in[0];
    const float* str_t1  = (const float*)d_in[1];
    const float* str_t2s = (const float*)d_in[2];
    const float* att_mat = (const float*)d_in[3];
    const float* W_bi    = (const float*)d_in[4];
    const float* b_bi    = (const float*)d_in[5];
    const int*   t1_ctx  = (const int*)d_in[6];
    const int*   t2_ctx  = (const int*)d_in[7];
    float* out = (float*)d_out;

    cudaFuncSetAttribute(gemm_kernel,
                         cudaFuncAttributeMaxDynamicSharedMemorySize, GEMM_SMEM);

    prep_kernel<<<K_CTX, D>>>(table, att_mat, t1_ctx);
    gemm_kernel<<<512, 256, GEMM_SMEM>>>(table, t2_ctx);
    score_kernel<<<256, 256>>>(table, str_t1, str_t2s, W_bi, b_bi,
                               t1_ctx, t2_ctx, out);
}

// round 7
// speedup vs baseline: 1.6000x; 1.4409x over previous
#include <cuda_runtime.h>

#define K_CTX 64
#define D     128
#define DS    200
#define STRIDE 132   // words; 16B-aligned rows; 8-lane LDS.128 phases conflict-free

__device__ float g_AM[K_CTX * D];        // AM = A @ att_mat
__device__ float g_A[K_CTX * D];         // raw A = table[t1_ctx]
__device__ float g_rowp[512 * K_CTX];    // row-sum partials per half-CTA (over its 32 cols)
__device__ float g_colm[256 * K_CTX];    // complete col sums per candidate

__device__ __forceinline__ float tanh_fast(float x) {
    x = fminf(fmaxf(x, -15.f), 15.f);
    float e = __expf(2.f * x);
    return __fdividef(e - 1.f, e + 1.f);
}

// ---- prep: AM = table[t1_ctx] @ att ; high-MLP split-d ----
__global__ __launch_bounds__(512)
void prep_kernel(const float* __restrict__ table,
                 const float* __restrict__ att,
                 const int* __restrict__ t1_ctx) {
    __shared__ float sA[D];
    __shared__ float partial[4 * D];
    const int k = blockIdx.x;
    const int t = threadIdx.x;
    const int j = t & 127;
    const int s = t >> 7;            // d-slice 0..3

    if (s == 0) sA[j] = table[(size_t)t1_ctx[k] * D + j];
    __syncthreads();

    const int d0 = s * 32;
    float a0 = 0.f, a1 = 0.f, a2 = 0.f, a3 = 0.f;
#pragma unroll
    for (int i = 0; i < 32; i += 4) {
        a0 = fmaf(sA[d0 + i + 0], att[(d0 + i + 0) * D + j], a0);
        a1 = fmaf(sA[d0 + i + 1], att[(d0 + i + 1) * D + j], a1);
        a2 = fmaf(sA[d0 + i + 2], att[(d0 + i + 2) * D + j], a2);
        a3 = fmaf(sA[d0 + i + 3], att[(d0 + i + 3) * D + j], a3);
    }
    partial[s * D + j] = (a0 + a1) + (a2 + a3);
    __syncthreads();

    if (s == 0) {
        g_AM[k * D + j] = partial[j] + partial[D + j] +
                          partial[2 * D + j] + partial[3 * D + j];
        g_A[k * D + j] = sA[j];
    }
}

// ---- gemm: half-candidate by N. CTA (c,h): all 64 AM rows x 32 B rows ----
__global__ __launch_bounds__(256, 4)
void gemm_kernel(const float* __restrict__ table,
                 const int* __restrict__ t2_ctx) {
    extern __shared__ float sm[];
    float* sAM     = sm;                      // 64*132
    float* sB      = sAM + K_CTX * STRIDE;    // 32*132
    float* colpart = sB + 32 * STRIDE;        // 8*32

    const int t    = threadIdx.x;
    const int bid  = blockIdx.x;
    const int c    = bid >> 1;
    const int m0   = (bid & 1) << 5;          // 0 or 32: which 32 B rows
    const int lane = t & 31;
    const int w    = t >> 5;

    // stage all 64 AM rows (L2-hot 32KB broadcast)
    for (int i = t; i < K_CTX * D; i += 256)
        sAM[(i >> 7) * STRIDE + (i & 127)] = g_AM[i];

    // gather this half's 32 B rows: 8 threads/row, float4
    {
        const int r = t >> 3, l = t & 7;
        size_t idx = (size_t)t2_ctx[c * K_CTX + m0 + r];
        const float4* src = (const float4*)(table + idx * D);
        float4* dst = (float4*)(sB + r * STRIDE);
#pragma unroll
        for (int q = 0; q < 4; ++q)
            dst[l + 8 * q] = src[l + 8 * q];
    }
    __syncthreads();

    // 64x32x128 GEMM: 4x2 tiles. rows ty+16p (p<4), cols tx+16q (q<2)
    const int tx = t & 15, ty = t >> 4;
    float acc[4][2];
#pragma unroll
    for (int p = 0; p < 4; ++p) { acc[p][0] = 0.f; acc[p][1] = 0.f; }

    {
        const float* pa = sAM + ty * STRIDE;
        const float* pb = sB  + tx * STRIDE;
#pragma unroll 4
        for (int dd = 0; dd < D; dd += 4) {
            float4 a0 = *(const float4*)(pa + dd);
            float4 a1 = *(const float4*)(pa + 16 * STRIDE + dd);
            float4 a2 = *(const float4*)(pa + 32 * STRIDE + dd);
            float4 a3 = *(const float4*)(pa + 48 * STRIDE + dd);
            float4 b0 = *(const float4*)(pb + dd);
            float4 b1 = *(const float4*)(pb + 16 * STRIDE + dd);
#define STEP(v) \
            acc[0][0] = fmaf(a0.v, b0.v, acc[0][0]); \
            acc[0][1] = fmaf(a0.v, b1.v, acc[0][1]); \
            acc[1][0] = fmaf(a1.v, b0.v, acc[1][0]); \
            acc[1][1] = fmaf(a1.v, b1.v, acc[1][1]); \
            acc[2][0] = fmaf(a2.v, b0.v, acc[2][0]); \
            acc[2][1] = fmaf(a2.v, b1.v, acc[2][1]); \
            acc[3][0] = fmaf(a3.v, b0.v, acc[3][0]); \
            acc[3][1] = fmaf(a3.v, b1.v, acc[3][1]);
            STEP(x) STEP(y) STEP(z) STEP(w)
#undef STEP
        }
    }

    float sv[4][2];
#pragma unroll
    for (int p = 0; p < 4; ++p) {
        sv[p][0] = tanh_fast(acc[p][0]);
        sv[p][1] = tanh_fast(acc[p][1]);
    }

    // row-sum partials (over this half's 32 m): shuffle across tx bits
#pragma unroll
    for (int p = 0; p < 4; ++p) {
        float rs = sv[p][0] + sv[p][1];
        rs += __shfl_xor_sync(0xffffffffu, rs, 1);
        rs += __shfl_xor_sync(0xffffffffu, rs, 2);
        rs += __shfl_xor_sync(0xffffffffu, rs, 4);
        rs += __shfl_xor_sync(0xffffffffu, rs, 8);
        if (tx == 0) g_rowp[bid * K_CTX + ty + 16 * p] = rs;
    }

    // col sums (over all 64 k): in-reg over p, xor16 pairs ty, 8 warp pieces
#pragma unroll
    for (int q = 0; q < 2; ++q) {
        float cs = (sv[0][q] + sv[1][q]) + (sv[2][q] + sv[3][q]);
        cs += __shfl_xor_sync(0xffffffffu, cs, 16);
        if (lane < 16) colpart[w * 32 + tx + 16 * q] = cs;
    }
    __syncthreads();
    if (t < 32) {
        float s = 0.f;
#pragma unroll
        for (int ww = 0; ww < 8; ++ww) s += colpart[ww * 32 + t];
        g_colm[c * K_CTX + m0 + t] = s;
    }
}

// ---- score: softmax + attention sums + bilinear + string branch ----
__global__ __launch_bounds__(256)
void score_kernel(const float* __restrict__ table,
                  const float* __restrict__ str_t1,
                  const float* __restrict__ str_t2s,
                  const float* __restrict__ W,
                  const float* __restrict__ b_bi,
                  const int* __restrict__ t2_ctx,
                  float* __restrict__ out) {
    __shared__ float rw[64], cw[64], nA[128], nB[128], red[256], part[32];
    __shared__ int sIdxB[64];

    const int t = threadIdx.x;
    const int c = blockIdx.x;
    const int lane = t & 31;

    float x1 = 0.f, x2 = 0.f;
    if (t < DS) { x1 = str_t1[t]; x2 = str_t2s[c * DS + t]; }

    if (t < 64) {
        rw[t] = (g_rowp[(2 * c) * K_CTX + t] + g_rowp[(2 * c + 1) * K_CTX + t])
                * (1.f / 64.f);
    } else if (t < 128) {
        const int m = t - 64;
        sIdxB[m] = t2_ctx[c * K_CTX + m];
        cw[m] = g_colm[c * K_CTX + m] * (1.f / 64.f);
    }
    __syncthreads();

    // dual softmax: warp0 -> rows, warp1 -> cols
    if (t < 64) {
        float* vec = (t < 32) ? rw : cw;
        float v0 = vec[lane], v1 = vec[lane + 32];
        float mx = fmaxf(v0, v1);
#pragma unroll
        for (int o = 16; o >= 1; o >>= 1)
            mx = fmaxf(mx, __shfl_xor_sync(0xffffffffu, mx, o));
        float e0 = __expf(v0 - mx), e1 = __expf(v1 - mx);
        float s = e0 + e1;
#pragma unroll
        for (int o = 16; o >= 1; o >>= 1)
            s += __shfl_xor_sync(0xffffffffu, s, o);
        float inv = __fdividef(1.f, s);
        vec[lane] = e0 * inv;
        vec[lane + 32] = e1 * inv;
    }
    __syncthreads();

    // nA from g_A (shared across all candidates, L2-hot, coalesced)
    if (t < 128) {
        float s0 = 0.f, s1 = 0.f, s2 = 0.f, s3 = 0.f;
#pragma unroll
        for (int k = 0; k < K_CTX; k += 4) {
            s0 = fmaf(rw[k + 0], g_A[(k + 0) * D + t], s0);
            s1 = fmaf(rw[k + 1], g_A[(k + 1) * D + t], s1);
            s2 = fmaf(rw[k + 2], g_A[(k + 2) * D + t], s2);
            s3 = fmaf(rw[k + 3], g_A[(k + 3) * D + t], s3);
        }
        nA[t] = (s0 + s1) + (s2 + s3);
    } else {
        // nB from candidate's table rows (L2-hot after gemm), 4-acc unrolled
        const int dd = t - 128;
        float s0 = 0.f, s1 = 0.f, s2 = 0.f, s3 = 0.f;
#pragma unroll
        for (int k = 0; k < K_CTX; k += 4) {
            s0 = fmaf(cw[k + 0], table[(size_t)sIdxB[k + 0] * D + dd], s0);
            s1 = fmaf(cw[k + 1], table[(size_t)sIdxB[k + 1] * D + dd], s1);
            s2 = fmaf(cw[k + 2], table[(size_t)sIdxB[k + 2] * D + dd], s2);
            s3 = fmaf(cw[k + 3], table[(size_t)sIdxB[k + 3] * D + dd], s3);
        }
        nB[dd] = (s0 + s1) + (s2 + s3);
    }
    __syncthreads();

    // bilinear: split d across the two thread halves
    {
        const int col = t & 127, half = t >> 7;
        float s = 0.f;
        const int d0 = half * 64;
#pragma unroll 4
        for (int d = d0; d < d0 + 64; ++d)
            s = fmaf(nA[d], W[d * D + col], s);
        red[t] = s;
    }
    __syncthreads();
    if (t < 128) {
        float v = (red[t] + red[t + 128]) * nB[t];
#pragma unroll
        for (int o = 16; o >= 1; o >>= 1)
            v += __shfl_xor_sync(0xffffffffu, v, o);
        if (lane == 0) part[t >> 5] = v;
    }
    __syncthreads();

    // string cosine branch
    {
        float p11 = x1 * x1, p22 = x2 * x2, p12 = x1 * x2;
#pragma unroll
        for (int o = 16; o >= 1; o >>= 1) {
            p11 += __shfl_xor_sync(0xffffffffu, p11, o);
            p22 += __shfl_xor_sync(0xffffffffu, p22, o);
            p12 += __shfl_xor_sync(0xffffffffu, p12, o);
        }
        const int w = t >> 5;
        if (lane == 0) { part[8 + w] = p11; part[16 + w] = p22; part[24 + w] = p12; }
    }
    __syncthreads();

    if (t == 0) {
        float con = part[0] + part[1] + part[2] + part[3] + b_bi[0];
        float s11 = 0.f, s22 = 0.f, s12 = 0.f;
#pragma unroll
        for (int w = 0; w < 8; ++w) {
            s11 += part[8 + w]; s22 += part[16 + w]; s12 += part[24 + w];
        }
        float n1 = fmaxf(sqrtf(s11), 1e-8f);
        float n2 = fmaxf(sqrtf(s22), 1e-8f);
        out[c] = 0.5f * (s12 / (n1 * n2)) + 0.5f * con;
    }
}

static const int GEMM_SMEM = (K_CTX * STRIDE + 32 * STRIDE + 8 * 32) * 4;

extern "C" void kernel_launch(void* const* d_in, const int* in_sizes, int n_in,
                              void* d_out, int out_size) {
    const float* table   = (const float*)d_in[0];
    const float* str_t1  = (const float*)d_in[1];
    const float* str_t2s = (const float*)d_in[2];
    const float* att_mat = (const float*)d_in[3];
    const float* W_bi    = (const float*)d_in[4];
    const float* b_bi    = (const float*)d_in[5];
    const int*   t1_ctx  = (const int*)d_in[6];
    const int*   t2_ctx  = (const int*)d_in[7];
    float* out = (float*)d_out;

    cudaFuncSetAttribute(gemm_kernel,
                         cudaFuncAttributeMaxDynamicSharedMemorySize, GEMM_SMEM);

    prep_kernel<<<K_CTX, 512>>>(table, att_mat, t1_ctx);
    gemm_kernel<<<512, 256, GEMM_SMEM>>>(table, t2_ctx);
    score_kernel<<<256, 256>>>(table, str_t1, str_t2s, W_bi, b_bi,
                               t2_ctx, out);
}